// round 8
// baseline (speedup 1.0000x reference)
#include <cuda_runtime.h>

#define NATOMS_MAX 20000
#define NEDGES_MAX 500000
#define LOG2E 1.4426950408889634f
#define PI_OVER_CUT (3.14159265358979323846f / 6.0f)

// scratch (accumulators + packed edge records)
__device__ uint2 g_rec[NEDGES_MAX];        // {D, tgt|s<<20|t<<21}
__device__ float g_g2s[NATOMS_MAX * 16];   // [n][src_species][8 etas]
__device__ float g_g4s[NATOMS_MAX * 48];   // [n][t][ii*5+p] moments, 64B t-blocks

// reconstruction matrix: cl_m(c) = sum_p CM[m][p] * c^p
// m = j*3+kk ; j: lambda {-1,+1}, kk: zeta {1,2,4} with 2^(1-z) folded in
__constant__ float CM[6][5] = {
    { 1.0f,  -1.0f, 0.0f,  0.0f,  0.0f  },   // (1-c)
    { 0.5f,  -1.0f, 0.5f,  0.0f,  0.0f  },   // (1-c)^2/2
    { 0.125f, -0.5f, 0.75f, -0.5f, 0.125f },  // (1-c)^4/8
    { 1.0f,   1.0f, 0.0f,  0.0f,  0.0f  },   // (1+c)
    { 0.5f,   1.0f, 0.5f,  0.0f,  0.0f  },   // (1+c)^2/2
    { 0.125f,  0.5f, 0.75f,  0.5f, 0.125f }   // (1+c)^4/8
};

__device__ __forceinline__ float ex2(float x) {
    float y; asm("ex2.approx.ftz.f32 %0, %1;" : "=f"(y) : "f"(x)); return y;
}
__device__ __forceinline__ void red4(float* p, float a, float b, float c, float d) {
    asm volatile("red.global.add.v4.f32 [%0], {%1,%2,%3,%4};"
                 :: "l"(p), "f"(a), "f"(b), "f"(c), "f"(d) : "memory");
}
__device__ __forceinline__ float fc(float R) {
    return fmaf(0.5f, __cosf(PI_OVER_CUT * R), 0.5f);
}

// Per edge: build packed record AND accumulate G2 (fused). R6-measured fastest form.
__global__ void __launch_bounds__(256) edge_k(const int* __restrict__ an,
                                              const int* __restrict__ ei,
                                              const float* __restrict__ D,
                                              const float* __restrict__ g2_etas,
                                              int E) {
    int e = blockIdx.x * blockDim.x + threadIdx.x;
    if (e >= E) return;
    int src = __ldg(ei + e);
    int tgt = __ldg(ei + E + e);
    int s = __ldg(an + src);
    int t = __ldg(an + tgt);
    float d = __ldg(D + e);

    g_rec[e] = make_uint2(__float_as_uint(d),
                          (unsigned)tgt | ((unsigned)s << 20) | ((unsigned)t << 21));

    float cut = fc(d);
    float md2 = -d * d * LOG2E;
    const float* eta = g2_etas + (s * 2 + t) * 8;
    float v[8];
#pragma unroll
    for (int k = 0; k < 8; k++) v[k] = cut * ex2(md2 * __ldg(eta + k));

    float* o = g_g2s + tgt * 16 + s * 8;
    red4(o,     v[0], v[1], v[2], v[3]);
    red4(o + 4, v[4], v[5], v[6], v[7]);
}

// G4 via moment accumulation: scatter S[ii][p] = rad_ii * cosphi^p (15 vals, 4 red4, 2 sectors)
__global__ void __launch_bounds__(256) g4_k(const int* __restrict__ id3_ba,
                                            const int* __restrict__ id3_ca,
                                            const float* __restrict__ cosphi,
                                            const float* __restrict__ g4_etas,
                                            int T) {
    int i = blockIdx.x * blockDim.x + threadIdx.x;
    if (i >= T) return;
    int ba = __ldg(id3_ba + i);
    int ca = __ldg(id3_ca + i);
    if (ba <= ca) return;                 // triplet dedup

    float cph = __ldg(cosphi + i);
    uint2 rb = g_rec[ba];
    uint2 rc = g_rec[ca];
    float Rba = __uint_as_float(rb.x);
    float Rca = __uint_as_float(rc.x);
    if (Rba >= 6.0f || Rca >= 6.0f) return;

    float Rbc2 = fmaf(Rba, Rba, fmaf(Rca, Rca, -2.0f * Rba * Rca * cph));
    float Rbc = sqrtf(fmaxf(Rbc2, 1e-12f));
    if (Rbc >= 6.0f) return;

    int aidx = rb.y & 0xFFFFF;
    int A    = (rb.y >> 21) & 1;          // central atom species
    int sb   = (rb.y >> 20) & 1;
    int sc   = (rc.y >> 20) & 1;
    int t = sb + sc;
    int k4 = A * 3 + t;

    float cut3 = fc(Rba) * fc(Rca) * fc(Rbc);
    float r2 = Rbc2 + Rba * Rba + Rca * Rca;

    const float* eta = g4_etas + k4 * 3;
    float mr2 = -r2 * LOG2E;
    float rad[3];
#pragma unroll
    for (int ii = 0; ii < 3; ii++) rad[ii] = ex2(mr2 * __ldg(eta + ii)) * cut3;

    float c1 = cph;
    float c2 = c1 * c1;
    float c3 = c2 * c1;
    float c4 = c2 * c2;
    float cp[5] = { 1.0f, c1, c2, c3, c4 };

    float v[15];
#pragma unroll
    for (int ii = 0; ii < 3; ii++)
#pragma unroll
        for (int p = 0; p < 5; p++)
            v[ii * 5 + p] = rad[ii] * cp[p];

    float* o = g_g4s + aidx * 48 + t * 16;   // 64B-aligned block: exactly 2 sectors
    red4(o,      v[0],  v[1],  v[2],  v[3]);
    red4(o + 4,  v[4],  v[5],  v[6],  v[7]);
    red4(o + 8,  v[8],  v[9],  v[10], v[11]);
    red4(o + 12, v[12], v[13], v[14], 0.0f);
}

// Reconstruct final [N,70] from scratch; one float2 per thread (R5-measured fastest form)
__global__ void __launch_bounds__(256) combine_k(float2* __restrict__ out, int n2_total) {
    int i = blockIdx.x * blockDim.x + threadIdx.x;
    if (i >= n2_total) return;
    int n = i / 35;
    int c = (i - n * 35) * 2;   // even col; pair never spans g2/g4 boundary
    float2 v;
    if (c < 16) {
        const float* g2 = g_g2s + n * 16;
        v.x = g2[(c & 1) * 8 + (c >> 1)];
        v.y = g2[((c + 1) & 1) * 8 + ((c + 1) >> 1)];
    } else {
        const float* S = g_g4s + n * 48;
        float r[2];
#pragma unroll
        for (int q = 0; q < 2; q++) {
            int idx = c - 16 + q;          // idx = m*3 + t, m = (ii*2+j)*3 + kk
            int t = idx % 3;
            int m = idx / 3;
            int ii = m / 6;
            int jk = ((m / 3) & 1) * 3 + (m % 3);   // j*3 + kk
            const float* s = S + t * 16 + ii * 5;
            float acc = CM[jk][0] * s[0];
            acc = fmaf(CM[jk][1], s[1], acc);
            acc = fmaf(CM[jk][2], s[2], acc);
            acc = fmaf(CM[jk][3], s[3], acc);
            acc = fmaf(CM[jk][4], s[4], acc);
            r[q] = acc;
        }
        v.x = r[0];
        v.y = r[1];
    }
    out[i] = v;
}

extern "C" void kernel_launch(void* const* d_in, const int* in_sizes, int n_in,
                              void* d_out, int out_size) {
    const int*   an       = (const int*)  d_in[0];
    const int*   ei       = (const int*)  d_in[1];
    const float* D        = (const float*)d_in[2];
    const int*   id3_ba   = (const int*)  d_in[3];
    const int*   id3_ca   = (const int*)  d_in[4];
    const float* cosphi   = (const float*)d_in[5];
    const float* g2_etas  = (const float*)d_in[6];
    const float* g4_etas  = (const float*)d_in[7];

    int E = in_sizes[2];
    int T = in_sizes[3];
    int N = in_sizes[0];

    void* p_g2s; cudaGetSymbolAddress(&p_g2s, g_g2s);
    void* p_g4s; cudaGetSymbolAddress(&p_g4s, g_g4s);
    cudaMemsetAsync(p_g2s, 0, (size_t)N * 16 * sizeof(float), 0);
    cudaMemsetAsync(p_g4s, 0, (size_t)N * 48 * sizeof(float), 0);

    edge_k<<<(E + 255) / 256, 256>>>(an, ei, D, g2_etas, E);
    g4_k<<<(T + 255) / 256, 256>>>(id3_ba, id3_ca, cosphi, g4_etas, T);

    int n2 = out_size / 2;
    combine_k<<<(n2 + 255) / 256, 256>>>((float2*)d_out, n2);
}

// round 9
// speedup vs baseline: 1.0538x; 1.0538x over previous
#include <cuda_runtime.h>

#define NATOMS_MAX 20000
#define NEDGES_MAX 500000
#define ANW 625                            // ceil(20000/32) species bitmask words
#define LOG2E 1.4426950408889634f
#define PI_OVER_CUT (3.14159265358979323846f / 6.0f)

// scratch (accumulators + packed edge records)
__device__ uint2    g_rec[NEDGES_MAX];        // {D, tgt|s<<20|t<<21}
__device__ float    g_g2s[NATOMS_MAX * 16];   // [n][src_species][8 etas]
__device__ float    g_g4s[NATOMS_MAX * 60];   // [n][t*20 + m], m=(ii*2+j)*3+kk
__device__ unsigned g_anbits[ANW];

__device__ __forceinline__ float ex2(float x) {
    float y; asm("ex2.approx.ftz.f32 %0, %1;" : "=f"(y) : "f"(x)); return y;
}
__device__ __forceinline__ void red4(float* p, float a, float b, float c, float d) {
    asm volatile("red.global.add.v4.f32 [%0], {%1,%2,%3,%4};"
                 :: "l"(p), "f"(a), "f"(b), "f"(c), "f"(d) : "memory");
}
__device__ __forceinline__ void red2(float* p, float a, float b) {
    asm volatile("red.global.add.v2.f32 [%0], {%1,%2};"
                 :: "l"(p), "f"(a), "f"(b) : "memory");
}
__device__ __forceinline__ float fc(float R) {
    return fmaf(0.5f, __cosf(PI_OVER_CUT * R), 0.5f);
}

// Pack species (0/1) into a bitmask (one warp-word per thread)
__global__ void anpack_k(const int* __restrict__ an, int N) {
    int w = blockIdx.x * blockDim.x + threadIdx.x;
    if (w >= ANW) return;
    unsigned bits = 0;
    int base = w * 32;
    int lim = min(32, N - base);
    for (int j = 0; j < lim; j++) bits |= ((unsigned)__ldg(an + base + j) & 1u) << j;
    g_anbits[w] = bits;
}

// Per edge: packed record + G2 accumulation. Species from smem bitmask (kills 32MB of
// random 4B gathers -> 1 coalesced 2.5KB block load).
__global__ void __launch_bounds__(256) edge_k(const int* __restrict__ ei,
                                              const float* __restrict__ D,
                                              const float* __restrict__ g2_etas,
                                              int E) {
    __shared__ unsigned s_bits[ANW];
    for (int w = threadIdx.x; w < ANW; w += blockDim.x) s_bits[w] = __ldg(g_anbits + w);
    __syncthreads();

    int e = blockIdx.x * blockDim.x + threadIdx.x;
    if (e >= E) return;
    int src = __ldg(ei + e);
    int tgt = __ldg(ei + E + e);
    int s = (s_bits[src >> 5] >> (src & 31)) & 1;
    int t = (s_bits[tgt >> 5] >> (tgt & 31)) & 1;
    float d = __ldg(D + e);

    g_rec[e] = make_uint2(__float_as_uint(d),
                          (unsigned)tgt | ((unsigned)s << 20) | ((unsigned)t << 21));

    float cut = fc(d);
    float md2 = -d * d * LOG2E;
    const float* eta = g2_etas + (s * 2 + t) * 8;
    float v[8];
#pragma unroll
    for (int k = 0; k < 8; k++) v[k] = cut * ex2(md2 * __ldg(eta + k));

    float* o = g_g2s + tgt * 16 + s * 8;
    red4(o,     v[0], v[1], v[2], v[3]);
    red4(o + 4, v[4], v[5], v[6], v[7]);
}

// G4: direct 18-value vector reduction (R6 form, stride-60 rows)
__global__ void __launch_bounds__(256) g4_k(const int* __restrict__ id3_ba,
                                            const int* __restrict__ id3_ca,
                                            const float* __restrict__ cosphi,
                                            const float* __restrict__ g4_etas,
                                            int T) {
    int i = blockIdx.x * blockDim.x + threadIdx.x;
    if (i >= T) return;
    int ba = __ldg(id3_ba + i);
    int ca = __ldg(id3_ca + i);
    if (ba <= ca) return;                 // triplet dedup

    float cph = __ldg(cosphi + i);
    uint2 rb = g_rec[ba];
    uint2 rc = g_rec[ca];
    float Rba = __uint_as_float(rb.x);
    float Rca = __uint_as_float(rc.x);
    if (Rba >= 6.0f || Rca >= 6.0f) return;

    float Rbc2 = fmaf(Rba, Rba, fmaf(Rca, Rca, -2.0f * Rba * Rca * cph));
    float Rbc = sqrtf(fmaxf(Rbc2, 1e-12f));
    if (Rbc >= 6.0f) return;

    int aidx = rb.y & 0xFFFFF;
    int A    = (rb.y >> 21) & 1;          // central atom species
    int sb   = (rb.y >> 20) & 1;
    int sc   = (rc.y >> 20) & 1;
    int t = sb + sc;
    int k4 = A * 3 + t;

    float cut3 = fc(Rba) * fc(Rca) * fc(Rbc);
    float r2 = Rbc2 + Rba * Rba + Rca * Rca;

    const float* eta = g4_etas + k4 * 3;
    float mr2 = -r2 * LOG2E;
    float rad[3];
#pragma unroll
    for (int ii = 0; ii < 3; ii++) rad[ii] = ex2(mr2 * __ldg(eta + ii)) * cut3;

    // zetas {1,2,4}, lambdas {-1,+1} (fixed): 2^(1-z)|1+l c|^z -> b, b^2/2, b^4/8
    float b0 = 1.0f - cph;
    float b1 = 1.0f + cph;
    float b0s = b0 * b0, b1s = b1 * b1;
    float cl[2][3] = {
        { b0, 0.5f * b0s, 0.125f * b0s * b0s },
        { b1, 0.5f * b1s, 0.125f * b1s * b1s } };

    float v[18];
#pragma unroll
    for (int ii = 0; ii < 3; ii++)
#pragma unroll
        for (int j = 0; j < 2; j++)
#pragma unroll
            for (int kk = 0; kk < 3; kk++)
                v[(ii * 2 + j) * 3 + kk] = rad[ii] * cl[j][kk];

    float* o = g_g4s + aidx * 60 + t * 20;   // 16B-aligned block of 18 (+2 pad)
    red4(o,      v[0],  v[1],  v[2],  v[3]);
    red4(o + 4,  v[4],  v[5],  v[6],  v[7]);
    red4(o + 8,  v[8],  v[9],  v[10], v[11]);
    red4(o + 12, v[12], v[13], v[14], v[15]);
    red2(o + 16, v[16], v[17]);
}

// Transpose scratch into final [N,70]; one float2 per thread (measured fastest: 6.56us)
__global__ void __launch_bounds__(256) combine_k(float2* __restrict__ out, int n2_total) {
    int i = blockIdx.x * blockDim.x + threadIdx.x;
    if (i >= n2_total) return;
    int n = i / 35;
    int c = (i - n * 35) * 2;   // even col; pair never spans g2/g4 boundary
    float2 v;
    if (c < 16) {
        const float* g2 = g_g2s + n * 16;
        v.x = g2[(c & 1) * 8 + (c >> 1)];
        v.y = g2[((c + 1) & 1) * 8 + ((c + 1) >> 1)];
    } else {
        const float* g4 = g_g4s + n * 60;
        int i0c = c - 16, i1c = c - 15;   // idx = m*3 + t ; storage: t*20 + m
        v.x = g4[(i0c % 3) * 20 + i0c / 3];
        v.y = g4[(i1c % 3) * 20 + i1c / 3];
    }
    out[i] = v;
}

extern "C" void kernel_launch(void* const* d_in, const int* in_sizes, int n_in,
                              void* d_out, int out_size) {
    const int*   an       = (const int*)  d_in[0];
    const int*   ei       = (const int*)  d_in[1];
    const float* D        = (const float*)d_in[2];
    const int*   id3_ba   = (const int*)  d_in[3];
    const int*   id3_ca   = (const int*)  d_in[4];
    const float* cosphi   = (const float*)d_in[5];
    const float* g2_etas  = (const float*)d_in[6];
    const float* g4_etas  = (const float*)d_in[7];

    int E = in_sizes[2];
    int T = in_sizes[3];
    int N = in_sizes[0];

    void* p_g2s; cudaGetSymbolAddress(&p_g2s, g_g2s);
    void* p_g4s; cudaGetSymbolAddress(&p_g4s, g_g4s);
    cudaMemsetAsync(p_g2s, 0, (size_t)N * 16 * sizeof(float), 0);
    cudaMemsetAsync(p_g4s, 0, (size_t)N * 60 * sizeof(float), 0);

    anpack_k<<<(ANW + 127) / 128, 128>>>(an, N);
    edge_k<<<(E + 255) / 256, 256>>>(ei, D, g2_etas, E);
    g4_k<<<(T + 255) / 256, 256>>>(id3_ba, id3_ca, cosphi, g4_etas, T);

    int n2 = out_size / 2;
    combine_k<<<(n2 + 255) / 256, 256>>>((float2*)d_out, n2);
}

// round 10
// speedup vs baseline: 1.1411x; 1.0828x over previous
#include <cuda_runtime.h>

#define NATOMS_MAX 20000
#define NEDGES_MAX 500000
#define LOG2E 1.4426950408889634f
#define PI_OVER_CUT (3.14159265358979323846f / 6.0f)

// scratch (accumulators + packed edge records)
__device__ uint2 g_rec[NEDGES_MAX];        // {D, tgt|s<<20|t<<21}
__device__ float g_g2s[NATOMS_MAX * 16];   // [n][src_species][8 etas]
__device__ float g_g4s[NATOMS_MAX * 48];   // [n][t][ii*5+p] moments, 64B t-blocks

__device__ __forceinline__ float ex2(float x) {
    float y; asm("ex2.approx.ftz.f32 %0, %1;" : "=f"(y) : "f"(x)); return y;
}
__device__ __forceinline__ void red4(float* p, float a, float b, float c, float d) {
    asm volatile("red.global.add.v4.f32 [%0], {%1,%2,%3,%4};"
                 :: "l"(p), "f"(a), "f"(b), "f"(c), "f"(d) : "memory");
}
__device__ __forceinline__ float fc(float R) {
    return fmaf(0.5f, __cosf(PI_OVER_CUT * R), 0.5f);
}

// Per edge: build packed record AND accumulate G2 (fused). R6-measured fastest form.
__global__ void __launch_bounds__(256) edge_k(const int* __restrict__ an,
                                              const int* __restrict__ ei,
                                              const float* __restrict__ D,
                                              const float* __restrict__ g2_etas,
                                              int E) {
    int e = blockIdx.x * blockDim.x + threadIdx.x;
    if (e >= E) return;
    int src = __ldg(ei + e);
    int tgt = __ldg(ei + E + e);
    int s = __ldg(an + src);
    int t = __ldg(an + tgt);
    float d = __ldg(D + e);

    g_rec[e] = make_uint2(__float_as_uint(d),
                          (unsigned)tgt | ((unsigned)s << 20) | ((unsigned)t << 21));

    float cut = fc(d);
    float md2 = -d * d * LOG2E;
    const float* eta = g2_etas + (s * 2 + t) * 8;
    float v[8];
#pragma unroll
    for (int k = 0; k < 8; k++) v[k] = cut * ex2(md2 * __ldg(eta + k));

    float* o = g_g2s + tgt * 16 + s * 8;
    red4(o,     v[0], v[1], v[2], v[3]);
    red4(o + 4, v[4], v[5], v[6], v[7]);
}

// G4 via moment accumulation: scatter S[ii][p] = rad_ii * c^p (15 vals, 4 red4, 2 sectors)
__global__ void __launch_bounds__(256) g4_k(const int* __restrict__ id3_ba,
                                            const int* __restrict__ id3_ca,
                                            const float* __restrict__ cosphi,
                                            const float* __restrict__ g4_etas,
                                            int T) {
    int i = blockIdx.x * blockDim.x + threadIdx.x;
    if (i >= T) return;
    int ba = __ldg(id3_ba + i);
    int ca = __ldg(id3_ca + i);
    if (ba <= ca) return;                 // triplet dedup

    float cph = __ldg(cosphi + i);
    uint2 rb = g_rec[ba];
    uint2 rc = g_rec[ca];
    float Rba = __uint_as_float(rb.x);
    float Rca = __uint_as_float(rc.x);
    if (Rba >= 6.0f || Rca >= 6.0f) return;

    float Rbc2 = fmaf(Rba, Rba, fmaf(Rca, Rca, -2.0f * Rba * Rca * cph));
    float Rbc = sqrtf(fmaxf(Rbc2, 1e-12f));
    if (Rbc >= 6.0f) return;

    int aidx = rb.y & 0xFFFFF;
    int A    = (rb.y >> 21) & 1;          // central atom species
    int sb   = (rb.y >> 20) & 1;
    int sc   = (rc.y >> 20) & 1;
    int t = sb + sc;
    int k4 = A * 3 + t;

    float cut3 = fc(Rba) * fc(Rca) * fc(Rbc);
    float r2 = Rbc2 + Rba * Rba + Rca * Rca;

    const float* eta = g4_etas + k4 * 3;
    float mr2 = -r2 * LOG2E;
    float rad[3];
#pragma unroll
    for (int ii = 0; ii < 3; ii++) rad[ii] = ex2(mr2 * __ldg(eta + ii)) * cut3;

    float c1 = cph;
    float c2 = c1 * c1;
    float c3 = c2 * c1;
    float c4 = c2 * c2;
    float cp[5] = { 1.0f, c1, c2, c3, c4 };

    float v[15];
#pragma unroll
    for (int ii = 0; ii < 3; ii++)
#pragma unroll
        for (int p = 0; p < 5; p++)
            v[ii * 5 + p] = rad[ii] * cp[p];

    float* o = g_g4s + aidx * 48 + t * 16;   // 64B block: exactly 2 sectors
    red4(o,      v[0],  v[1],  v[2],  v[3]);
    red4(o + 4,  v[4],  v[5],  v[6],  v[7]);
    red4(o + 8,  v[8],  v[9],  v[10], v[11]);
    red4(o + 12, v[12], v[13], v[14], 0.0f);
}

// Reconstruct final [N,70]; one float2/thread; binomial reconstruction in registers
// (no constant-table indexing, no branches).
__global__ void __launch_bounds__(256) combine_k(float2* __restrict__ out, int n2_total) {
    int i = blockIdx.x * blockDim.x + threadIdx.x;
    if (i >= n2_total) return;
    int n = i / 35;
    int c = (i - n * 35) * 2;   // even col; pair never spans g2/g4 boundary
    float2 v;
    if (c < 16) {
        const float* g2 = g_g2s + n * 16;
        v.x = g2[(c & 1) * 8 + (c >> 1)];
        v.y = g2[((c + 1) & 1) * 8 + ((c + 1) >> 1)];
    } else {
        const float* g4 = g_g4s + n * 48;
        float r[2];
#pragma unroll
        for (int q = 0; q < 2; q++) {
            int idx = c - 16 + q;          // idx = m*3 + t ; m = (ii*2+j)*3 + kk
            int t = idx % 3;
            int m = idx / 3;
            int ii = m / 6;
            int j  = (m / 3) & 1;          // lambda: 0 -> -1, 1 -> +1
            int kk = m % 3;                // zeta: 1, 2, 4
            const float* s = g4 + t * 16 + ii * 5;
            float S0 = s[0], S1 = s[1], S2 = s[2], S3 = s[3], S4 = s[4];
            float lS1 = j ? S1 : -S1;
            float lS3 = j ? S3 : -S3;
            // 2^(1-z) * sum(rad * (1 + l c)^z) via binomial expansion of moments
            float v1 = S0 + lS1;
            float v2 = 0.5f * fmaf(2.0f, lS1, S0 + S2);
            float v4 = 0.125f * (fmaf(6.0f, S2, S0 + S4) + 4.0f * (lS1 + lS3));
            r[q] = (kk == 0) ? v1 : ((kk == 1) ? v2 : v4);
        }
        v.x = r[0];
        v.y = r[1];
    }
    out[i] = v;
}

extern "C" void kernel_launch(void* const* d_in, const int* in_sizes, int n_in,
                              void* d_out, int out_size) {
    const int*   an       = (const int*)  d_in[0];
    const int*   ei       = (const int*)  d_in[1];
    const float* D        = (const float*)d_in[2];
    const int*   id3_ba   = (const int*)  d_in[3];
    const int*   id3_ca   = (const int*)  d_in[4];
    const float* cosphi   = (const float*)d_in[5];
    const float* g2_etas  = (const float*)d_in[6];
    const float* g4_etas  = (const float*)d_in[7];

    int E = in_sizes[2];
    int T = in_sizes[3];
    int N = in_sizes[0];

    void* p_g2s; cudaGetSymbolAddress(&p_g2s, g_g2s);
    void* p_g4s; cudaGetSymbolAddress(&p_g4s, g_g4s);
    cudaMemsetAsync(p_g2s, 0, (size_t)N * 16 * sizeof(float), 0);
    cudaMemsetAsync(p_g4s, 0, (size_t)N * 48 * sizeof(float), 0);

    edge_k<<<(E + 255) / 256, 256>>>(an, ei, D, g2_etas, E);
    g4_k<<<(T + 255) / 256, 256>>>(id3_ba, id3_ca, cosphi, g4_etas, T);

    int n2 = out_size / 2;
    combine_k<<<(n2 + 255) / 256, 256>>>((float2*)d_out, n2);
}

// round 11
// speedup vs baseline: 1.2762x; 1.1184x over previous
#include <cuda_runtime.h>

#define NATOMS_MAX 20000
#define NEDGES_MAX 500000
#define LOG2E 1.4426950408889634f
#define PI_OVER_CUT (3.14159265358979323846f / 6.0f)

// scratch (accumulators + packed edge records)
__device__ uint2 g_rec[NEDGES_MAX];        // {D, tgt|s<<20|t<<21}
__device__ float g_g2s[NATOMS_MAX * 16];   // [n][src_species][8 etas]
__device__ float g_g4s[NATOMS_MAX * 48];   // [n][t][ii*5+p] moments, 64B t-blocks

__device__ __forceinline__ float ex2(float x) {
    float y; asm("ex2.approx.ftz.f32 %0, %1;" : "=f"(y) : "f"(x)); return y;
}
__device__ __forceinline__ void red4(float* p, float a, float b, float c, float d) {
    asm volatile("red.global.add.v4.f32 [%0], {%1,%2,%3,%4};"
                 :: "l"(p), "f"(a), "f"(b), "f"(c), "f"(d) : "memory");
}
__device__ __forceinline__ float fc(float R) {
    return fmaf(0.5f, __cosf(PI_OVER_CUT * R), 0.5f);
}

// k1: heterogeneous blocks — [0, recB): build packed edge records;
//     [recB, recB+zeroB): zero the accumulators (overlaps record-gather latency)
__global__ void __launch_bounds__(256) rec_zero_k(const int* __restrict__ an,
                                                  const int* __restrict__ ei,
                                                  const float* __restrict__ D,
                                                  int E, int recB, int N) {
    int b = blockIdx.x;
    if (b < recB) {
        int e = b * 256 + threadIdx.x;
        if (e >= E) return;
        int src = __ldg(ei + e);
        int tgt = __ldg(ei + E + e);
        int s = __ldg(an + src);
        int t = __ldg(an + tgt);
        float d = __ldg(D + e);
        g_rec[e] = make_uint2(__float_as_uint(d),
                              (unsigned)tgt | ((unsigned)s << 20) | ((unsigned)t << 21));
    } else {
        // zero: g_g2s has N*16 floats = N*4 float4; g_g4s has N*48 = N*12 float4
        int i = (b - recB) * 256 + threadIdx.x;
        float4 z = make_float4(0.f, 0.f, 0.f, 0.f);
        int n4g2 = N * 4;
        if (i < n4g2) reinterpret_cast<float4*>(g_g2s)[i] = z;
        int n4g4 = N * 12;
#pragma unroll
        for (int r = 0; r < 3; r++) {
            int j = i + r * n4g2;
            if (j < n4g4) reinterpret_cast<float4*>(g_g4s)[j] = z;
        }
    }
}

// k2: heterogeneous blocks — [0, g4B): G4 triplets (moment scatter);
//     [g4B, g4B+g2B): G2 edges streaming packed records (coalesced, no gathers)
__global__ void __launch_bounds__(256) fused_k(const int* __restrict__ id3_ba,
                                               const int* __restrict__ id3_ca,
                                               const float* __restrict__ cosphi,
                                               const float* __restrict__ g4_etas,
                                               const float* __restrict__ g2_etas,
                                               int T, int E, int g4B) {
    int b = blockIdx.x;
    if (b < g4B) {
        // ---- G4 path ----
        int i = b * 256 + threadIdx.x;
        if (i >= T) return;
        int ba = __ldg(id3_ba + i);
        int ca = __ldg(id3_ca + i);
        if (ba <= ca) return;                 // triplet dedup

        float cph = __ldg(cosphi + i);
        uint2 rb = g_rec[ba];
        uint2 rc = g_rec[ca];
        float Rba = __uint_as_float(rb.x);
        float Rca = __uint_as_float(rc.x);
        if (Rba >= 6.0f || Rca >= 6.0f) return;

        float Rbc2 = fmaf(Rba, Rba, fmaf(Rca, Rca, -2.0f * Rba * Rca * cph));
        float Rbc = sqrtf(fmaxf(Rbc2, 1e-12f));
        if (Rbc >= 6.0f) return;

        int aidx = rb.y & 0xFFFFF;
        int A    = (rb.y >> 21) & 1;          // central atom species
        int sb   = (rb.y >> 20) & 1;
        int sc   = (rc.y >> 20) & 1;
        int t = sb + sc;
        int k4 = A * 3 + t;

        float cut3 = fc(Rba) * fc(Rca) * fc(Rbc);
        float r2 = Rbc2 + Rba * Rba + Rca * Rca;

        const float* eta = g4_etas + k4 * 3;
        float mr2 = -r2 * LOG2E;
        float rad[3];
#pragma unroll
        for (int ii = 0; ii < 3; ii++) rad[ii] = ex2(mr2 * __ldg(eta + ii)) * cut3;

        float c1 = cph;
        float c2 = c1 * c1;
        float c3 = c2 * c1;
        float c4 = c2 * c2;
        float cp[5] = { 1.0f, c1, c2, c3, c4 };

        float v[15];
#pragma unroll
        for (int ii = 0; ii < 3; ii++)
#pragma unroll
            for (int p = 0; p < 5; p++)
                v[ii * 5 + p] = rad[ii] * cp[p];

        float* o = g_g4s + aidx * 48 + t * 16;   // 64B block: exactly 2 sectors
        red4(o,      v[0],  v[1],  v[2],  v[3]);
        red4(o + 4,  v[4],  v[5],  v[6],  v[7]);
        red4(o + 8,  v[8],  v[9],  v[10], v[11]);
        red4(o + 12, v[12], v[13], v[14], 0.0f);
    } else {
        // ---- G2 path: stream packed records, no random gathers ----
        int e = (b - g4B) * 256 + threadIdx.x;
        if (e >= E) return;
        uint2 r = g_rec[e];
        float d = __uint_as_float(r.x);
        int tgt = r.y & 0xFFFFF;
        int s   = (r.y >> 20) & 1;
        int t   = (r.y >> 21) & 1;

        float cut = fc(d);
        float md2 = -d * d * LOG2E;
        const float* eta = g2_etas + (s * 2 + t) * 8;
        float v[8];
#pragma unroll
        for (int k = 0; k < 8; k++) v[k] = cut * ex2(md2 * __ldg(eta + k));

        float* o = g_g2s + tgt * 16 + s * 8;
        red4(o,     v[0], v[1], v[2], v[3]);
        red4(o + 4, v[4], v[5], v[6], v[7]);
    }
}

// k3: reconstruct final [N,70]; one float2/thread; branch-free binomial reconstruction
__global__ void __launch_bounds__(256) combine_k(float2* __restrict__ out, int n2_total) {
    int i = blockIdx.x * blockDim.x + threadIdx.x;
    if (i >= n2_total) return;
    int n = i / 35;
    int c = (i - n * 35) * 2;   // even col; pair never spans g2/g4 boundary
    float2 v;
    if (c < 16) {
        const float* g2 = g_g2s + n * 16;
        v.x = g2[(c & 1) * 8 + (c >> 1)];
        v.y = g2[((c + 1) & 1) * 8 + ((c + 1) >> 1)];
    } else {
        const float* g4 = g_g4s + n * 48;
        float r[2];
#pragma unroll
        for (int q = 0; q < 2; q++) {
            int idx = c - 16 + q;          // idx = m*3 + t ; m = (ii*2+j)*3 + kk
            int t = idx % 3;
            int m = idx / 3;
            int ii = m / 6;
            int j  = (m / 3) & 1;          // lambda: 0 -> -1, 1 -> +1
            int kk = m % 3;                // zeta: 1, 2, 4
            const float* s = g4 + t * 16 + ii * 5;
            float S0 = s[0], S1 = s[1], S2 = s[2], S3 = s[3], S4 = s[4];
            float lS1 = j ? S1 : -S1;
            float lS3 = j ? S3 : -S3;
            float v1 = S0 + lS1;
            float v2 = 0.5f * fmaf(2.0f, lS1, S0 + S2);
            float v4 = 0.125f * (fmaf(6.0f, S2, S0 + S4) + 4.0f * (lS1 + lS3));
            r[q] = (kk == 0) ? v1 : ((kk == 1) ? v2 : v4);
        }
        v.x = r[0];
        v.y = r[1];
    }
    out[i] = v;
}

extern "C" void kernel_launch(void* const* d_in, const int* in_sizes, int n_in,
                              void* d_out, int out_size) {
    const int*   an       = (const int*)  d_in[0];
    const int*   ei       = (const int*)  d_in[1];
    const float* D        = (const float*)d_in[2];
    const int*   id3_ba   = (const int*)  d_in[3];
    const int*   id3_ca   = (const int*)  d_in[4];
    const float* cosphi   = (const float*)d_in[5];
    const float* g2_etas  = (const float*)d_in[6];
    const float* g4_etas  = (const float*)d_in[7];

    int E = in_sizes[2];
    int T = in_sizes[3];
    int N = in_sizes[0];

    int recB  = (E + 255) / 256;
    int zeroB = (N * 4 + 255) / 256;        // N*4 float4 stride covers both arrays (x4 loop)
    rec_zero_k<<<recB + zeroB, 256>>>(an, ei, D, E, recB, N);

    int g4B = (T + 255) / 256;
    int g2B = (E + 255) / 256;
    fused_k<<<g4B + g2B, 256>>>(id3_ba, id3_ca, cosphi, g4_etas, g2_etas, T, E, g4B);

    int n2 = out_size / 2;
    combine_k<<<(n2 + 255) / 256, 256>>>((float2*)d_out, n2);
}